// round 14
// baseline (speedup 1.0000x reference)
#include <cuda_runtime.h>
#include <cuda_bf16.h>
#include <cstdint>

// Problem constants
#define D_MODEL   1024
#define NUM_HEADS 16
#define HEAD_DIM  64
#define BATCH     4
#define SEQ       2048
#define M_TOTAL   (BATCH * SEQ)          // 8192 rows
#define QKV_E     (BATCH * NUM_HEADS * SEQ * HEAD_DIM)

// Pre-split bf16 scratch (allocation-free rule: __device__ globals)
__device__ __nv_bfloat16 g_xh[M_TOTAL * D_MODEL],  g_xl[M_TOTAL * D_MODEL];
__device__ __nv_bfloat16 g_wqh[D_MODEL * D_MODEL], g_wql[D_MODEL * D_MODEL];
__device__ __nv_bfloat16 g_wkh[D_MODEL * D_MODEL], g_wkl[D_MODEL * D_MODEL];
__device__ __nv_bfloat16 g_wvh[D_MODEL * D_MODEL], g_wvl[D_MODEL * D_MODEL];
__device__ __nv_bfloat16 g_woh[D_MODEL * D_MODEL], g_wol[D_MODEL * D_MODEL];
__device__ __nv_bfloat16 g_qh[QKV_E], g_ql[QKV_E];      // [B,H,S,Dh], Q pre-scaled
__device__ __nv_bfloat16 g_kh[QKV_E], g_kl[QKV_E];
__device__ __nv_bfloat16 g_vh[QKV_E], g_vl[QKV_E];
__device__ __nv_bfloat16 g_oh[M_TOTAL * D_MODEL], g_ol[M_TOTAL * D_MODEL];

// ===========================================================================
// helpers
// ===========================================================================
static __device__ __forceinline__ uint32_t smem_u32(const void* p) {
    uint32_t a;
    asm("{ .reg .u64 t; cvta.to.shared.u64 t, %1; cvt.u32.u64 %0, t; }"
        : "=r"(a) : "l"(p));
    return a;
}

static __device__ __forceinline__ void ldsm_x4(uint32_t (&r)[4], uint32_t addr) {
    asm volatile("ldmatrix.sync.aligned.m8n8.x4.shared.b16 {%0,%1,%2,%3}, [%4];"
                 : "=r"(r[0]), "=r"(r[1]), "=r"(r[2]), "=r"(r[3]) : "r"(addr));
}

static __device__ __forceinline__ void ldsm_x4_t(uint32_t (&r)[4], uint32_t addr) {
    asm volatile("ldmatrix.sync.aligned.m8n8.x4.trans.shared.b16 {%0,%1,%2,%3}, [%4];"
                 : "=r"(r[0]), "=r"(r[1]), "=r"(r[2]), "=r"(r[3]) : "r"(addr));
}

static __device__ __forceinline__ void mma16816(float (&d)[4],
                                                const uint32_t (&a)[4],
                                                const uint32_t* b)
{
    asm volatile(
        "mma.sync.aligned.m16n8k16.row.col.f32.bf16.bf16.f32 "
        "{%0,%1,%2,%3}, {%4,%5,%6,%7}, {%8,%9}, {%0,%1,%2,%3};"
        : "+f"(d[0]), "+f"(d[1]), "+f"(d[2]), "+f"(d[3])
        : "r"(a[0]), "r"(a[1]), "r"(a[2]), "r"(a[3]), "r"(b[0]), "r"(b[1]));
}

#define CP16(dst, src) \
    asm volatile("cp.async.cg.shared.global [%0], [%1], 16;" \
                 :: "r"(dst), "l"(src) : "memory")
#define CP_COMMIT() asm volatile("cp.async.commit_group;" ::: "memory")
#define CP_WAIT0()  asm volatile("cp.async.wait_group 0;" ::: "memory")
#define CP_WAIT1()  asm volatile("cp.async.wait_group 1;" ::: "memory")

static __device__ __forceinline__ uint32_t pack_bf16x2(float a, float b) {
    __nv_bfloat162 t = __floats2bfloat162_rn(a, b);
    return *reinterpret_cast<uint32_t*>(&t);
}

static __device__ __forceinline__ void split2_store(__nv_bfloat16* H, __nv_bfloat16* L,
                                                    size_t idx, float v0, float v1)
{
    __nv_bfloat16 h0 = __float2bfloat16(v0), h1 = __float2bfloat16(v1);
    *(uint32_t*)(H + idx) = pack_bf16x2(v0, v1);
    *(uint32_t*)(L + idx) = pack_bf16x2(v0 - __bfloat162float(h0),
                                        v1 - __bfloat162float(h1));
}

// ===========================================================================
// split pass: fp32 -> hi/lo bf16
// ===========================================================================
__global__ __launch_bounds__(256)
void split_kernel(const float* __restrict__ src, __nv_bfloat16* __restrict__ H,
                  __nv_bfloat16* __restrict__ L, int n4)
{
    for (int i = blockIdx.x * blockDim.x + threadIdx.x; i < n4;
         i += gridDim.x * blockDim.x) {
        float4 v = __ldg((const float4*)src + i);
        split2_store(H, L, (size_t)i * 4 + 0, v.x, v.y);
        split2_store(H, L, (size_t)i * 4 + 2, v.z, v.w);
    }
}

// ===========================================================================
// GEMM: C = (Ah+Al) @ (Bh+Bl)^T + bias   (3-term bf16 split, HMMA)
// A: [M,1024] bf16 hi/lo. B(W): [1024,1024] row-major (N x K) hi/lo.
// CTA 128x128, BK=32, double-buffered cp.async staging.
// mode 0: fp32 out [M,1024].  mode 1: split QKV out [B,H,S,Dh], val*scale.
// ===========================================================================
#define STRIDE  40                        // padded smem row (bf16 elems), 80B
#define TILE_E  (128 * STRIDE)            // 5120 elems per tile
#define STAGE_E (4 * TILE_E)              // Ah,Al,Bh,Bl
#define GEMM_SMEM_B (2 * STAGE_E * 2)     // bytes = 81920

extern __shared__ __nv_bfloat16 dsm[];

static __device__ __forceinline__ void gemm_issue(const __nv_bfloat16* Ah,
                                                  const __nv_bfloat16* Al,
                                                  const __nv_bfloat16* Bh,
                                                  const __nv_bfloat16* Bl,
                                                  uint32_t sb, int stage,
                                                  int bm, int bn, int k0, int tid)
{
    const uint32_t base = sb + (uint32_t)(stage * STAGE_E) * 2;
    #pragma unroll
    for (int i = 0; i < 2; i++) {
        const int idx = tid + i * 256;          // 0..511
        const int row = idx >> 2, c = idx & 3;  // row 0..127, 16B chunk 0..3
        const size_t gofs = (size_t)row * D_MODEL + k0 + c * 8;
        const uint32_t sofs = (uint32_t)(row * STRIDE + c * 8) * 2;
        CP16(base + 0 * TILE_E * 2 + sofs, Ah + (size_t)bm * D_MODEL + gofs);
        CP16(base + 1 * TILE_E * 2 + sofs, Al + (size_t)bm * D_MODEL + gofs);
        CP16(base + 2 * TILE_E * 2 + sofs, Bh + (size_t)bn * D_MODEL + gofs);
        CP16(base + 3 * TILE_E * 2 + sofs, Bl + (size_t)bn * D_MODEL + gofs);
    }
}

static __device__ __forceinline__ void gemm_tc_body(const __nv_bfloat16* __restrict__ Ah,
                                                    const __nv_bfloat16* __restrict__ Al,
                                                    const __nv_bfloat16* __restrict__ Bh,
                                                    const __nv_bfloat16* __restrict__ Bl,
                                                    const float* __restrict__ bias,
                                                    float* __restrict__ Cf,
                                                    __nv_bfloat16* __restrict__ Ch,
                                                    __nv_bfloat16* __restrict__ Cl,
                                                    int mode, float scale)
{
    const uint32_t sb = smem_u32(dsm);
    const int tid  = threadIdx.x;
    const int wid  = tid >> 5;
    const int lane = tid & 31;
    const int bm = blockIdx.y * 128;
    const int bn = blockIdx.x * 128;
    const int warp_m = (wid & 1) * 64;
    const int warp_n = (wid >> 1) * 32;

    float acc[4][4][4];
    #pragma unroll
    for (int i = 0; i < 4; i++)
        #pragma unroll
        for (int j = 0; j < 4; j++)
            #pragma unroll
            for (int c = 0; c < 4; c++) acc[i][j][c] = 0.f;

    gemm_issue(Ah, Al, Bh, Bl, sb, 0, bm, bn, 0, tid);
    CP_COMMIT();

    #pragma unroll 1
    for (int chunk = 0; chunk < D_MODEL / 32; chunk++) {
        const int cur = chunk & 1;
        if (chunk + 1 < D_MODEL / 32) {
            gemm_issue(Ah, Al, Bh, Bl, sb, cur ^ 1, bm, bn, (chunk + 1) * 32, tid);
            CP_COMMIT();
            CP_WAIT1();
        } else {
            CP_WAIT0();
        }
        __syncthreads();

        const uint32_t uAh = sb + (uint32_t)(cur * STAGE_E + 0 * TILE_E) * 2;
        const uint32_t uAl = sb + (uint32_t)(cur * STAGE_E + 1 * TILE_E) * 2;
        const uint32_t uBh = sb + (uint32_t)(cur * STAGE_E + 2 * TILE_E) * 2;
        const uint32_t uBl = sb + (uint32_t)(cur * STAGE_E + 3 * TILE_E) * 2;

        #pragma unroll
        for (int ks = 0; ks < 2; ks++) {
            uint32_t ah[4][4], al[4][4];
            {
                const int row = ((lane >> 3) & 1) * 8 + (lane & 7);
                const int kk  = ks * 16 + ((lane >> 4) & 1) * 8;
                #pragma unroll
                for (int mf = 0; mf < 4; mf++) {
                    const uint32_t off =
                        (uint32_t)(((warp_m + mf * 16 + row) * STRIDE + kk) * 2);
                    ldsm_x4(ah[mf], uAh + off);
                    ldsm_x4(al[mf], uAl + off);
                }
            }
            uint32_t bh[2][4], bl[2][4];
            {
                const int row = ((lane >> 4) & 1) * 8 + (lane & 7);
                const int kk  = ks * 16 + ((lane >> 3) & 1) * 8;
                #pragma unroll
                for (int nb = 0; nb < 2; nb++) {
                    const uint32_t off =
                        (uint32_t)(((warp_n + nb * 16 + row) * STRIDE + kk) * 2);
                    ldsm_x4(bh[nb], uBh + off);
                    ldsm_x4(bl[nb], uBl + off);
                }
            }
            #pragma unroll
            for (int mf = 0; mf < 4; mf++)
                #pragma unroll
                for (int nf = 0; nf < 4; nf++) {
                    const int nb = nf >> 1, o = (nf & 1) * 2;
                    mma16816(acc[mf][nf], ah[mf], &bh[nb][o]);
                    mma16816(acc[mf][nf], ah[mf], &bl[nb][o]);
                    mma16816(acc[mf][nf], al[mf], &bh[nb][o]);
                }
        }
        __syncthreads();
    }

    const int er = lane >> 2;
    const int ec = (lane & 3) * 2;
    #pragma unroll
    for (int mf = 0; mf < 4; mf++) {
        #pragma unroll
        for (int nf = 0; nf < 4; nf++) {
            const int n = bn + warp_n + nf * 8 + ec;
            const float b0 = __ldg(bias + n), b1 = __ldg(bias + n + 1);
            #pragma unroll
            for (int half = 0; half < 2; half++) {
                const int m = bm + warp_m + mf * 16 + er + half * 8;
                const float v0 = (acc[mf][nf][half * 2 + 0] + b0) * scale;
                const float v1 = (acc[mf][nf][half * 2 + 1] + b1) * scale;
                if (mode == 0) {
                    float2 r; r.x = v0; r.y = v1;
                    *(float2*)(Cf + (size_t)m * D_MODEL + n) = r;
                } else {
                    const int bb = m >> 11, s = m & 2047;
                    const int h = n >> 6,  d = n & 63;
                    const size_t idx =
                        (((size_t)(bb * NUM_HEADS + h) * SEQ + s) << 6) + d;
                    split2_store(Ch, Cl, idx, v0, v1);
                }
            }
        }
    }
}

__global__ __launch_bounds__(256)
void qkv_gemm_kernel(const float* __restrict__ bq, const float* __restrict__ bk,
                     const float* __restrict__ bv)
{
    if (blockIdx.z == 0)
        gemm_tc_body(g_xh, g_xl, g_wqh, g_wql, bq, nullptr, g_qh, g_ql, 1, 0.125f);
    else if (blockIdx.z == 1)
        gemm_tc_body(g_xh, g_xl, g_wkh, g_wkl, bk, nullptr, g_kh, g_kl, 1, 1.0f);
    else
        gemm_tc_body(g_xh, g_xl, g_wvh, g_wvl, bv, nullptr, g_vh, g_vl, 1, 1.0f);
}

__global__ __launch_bounds__(256)
void out_gemm_kernel(const float* __restrict__ bo, float* __restrict__ out)
{
    gemm_tc_body(g_oh, g_ol, g_woh, g_wol, bo, out, nullptr, nullptr, 0, 1.0f);
}

// ===========================================================================
// Tensor-core flash attention, pre-split inputs, cp.async double-buffered.
// CTA: 64 q-rows, 4 warps. K/V tiles of 64 keys.
// ===========================================================================
#define AT_STRIDE 72                       // bf16 elems per row (144B, 16B mult)
#define AT_TILE   (64 * AT_STRIDE)         // 4608 elems
#define AT_STAGE  (4 * AT_TILE)            // Kh,Kl,Vh,Vl
#define ATTN_SMEM_B (2 * AT_STAGE * 2)     // 73728 bytes

static __device__ __forceinline__ void attn_issue(uint32_t sb, int stage,
                                                  size_t kvbase, int kt, int tid)
{
    const uint32_t base = sb + (uint32_t)(stage * AT_STAGE) * 2;
    const __nv_bfloat16* srcs[4] = { g_kh, g_kl, g_vh, g_vl };
    #pragma unroll
    for (int i = 0; i < 16; i++) {
        const int idx = tid + i * 128;             // 0..2047
        const int arr = idx >> 9;                  // 0..3
        const int j   = idx & 511;
        const int row = j >> 3, c = j & 7;
        const __nv_bfloat16* src =
            srcs[arr] + kvbase + (size_t)(kt * 64 + row) * HEAD_DIM + c * 8;
        const uint32_t dst =
            base + (uint32_t)(arr * AT_TILE + row * AT_STRIDE + c * 8) * 2;
        CP16(dst, src);
    }
}

__global__ __launch_bounds__(128)
void attn_kernel()
{
    const uint32_t sb = smem_u32(dsm);

    const int bh    = blockIdx.x;            // b*16 + h
    const int qbase = blockIdx.y * 64;
    const int tid   = threadIdx.x;
    const int wid   = tid >> 5;
    const int lane  = tid & 31;
    const int warp_m = wid * 16;

    const size_t kvbase = (size_t)bh * SEQ * HEAD_DIM;

    // ---- stage Q (already scaled+split) into stage-0 Kh/Kl area
    #pragma unroll
    for (int i = 0; i < 8; i++) {
        const int idx = tid + i * 128;           // 0..1023
        const int arr = idx >> 9;                // 0: hi, 1: lo
        const int j   = idx & 511;
        const int row = j >> 3, c = j & 7;
        const __nv_bfloat16* src =
            (arr == 0 ? g_qh : g_ql) + kvbase + (size_t)(qbase + row) * HEAD_DIM + c * 8;
        const uint32_t dst = sb + (uint32_t)(arr * AT_TILE + row * AT_STRIDE + c * 8) * 2;
        CP16(dst, src);
    }
    CP_COMMIT();
    CP_WAIT0();
    __syncthreads();

    uint32_t qh[4][4], ql[4][4];
    {
        const int row = warp_m + ((lane >> 3) & 1) * 8 + (lane & 7);
        #pragma unroll
        for (int ks = 0; ks < 4; ks++) {
            const int kk = ks * 16 + ((lane >> 4) & 1) * 8;
            const uint32_t off = (uint32_t)((row * AT_STRIDE + kk) * 2);
            ldsm_x4(qh[ks], sb + off);
            ldsm_x4(ql[ks], sb + (uint32_t)(AT_TILE * 2) + off);
        }
    }
    __syncthreads();

    float o[8][4];
    #pragma unroll
    for (int nf = 0; nf < 8; nf++)
        #pragma unroll
        for (int c = 0; c < 4; c++) o[nf][c] = 0.f;
    float m0 = -1e30f, m1 = -1e30f, l0 = 0.f, l1 = 0.f;

    attn_issue(sb, 0, kvbase, 0, tid);
    CP_COMMIT();

    #pragma unroll 1
    for (int kt = 0; kt < SEQ / 64; kt++) {
        const int cur = kt & 1;
        if (kt + 1 < SEQ / 64) {
            attn_issue(sb, cur ^ 1, kvbase, kt + 1, tid);
            CP_COMMIT();
            CP_WAIT1();
        } else {
            CP_WAIT0();
        }
        __syncthreads();

        const uint32_t uKh = sb + (uint32_t)(cur * AT_STAGE + 0 * AT_TILE) * 2;
        const uint32_t uKl = sb + (uint32_t)(cur * AT_STAGE + 1 * AT_TILE) * 2;
        const uint32_t uVh = sb + (uint32_t)(cur * AT_STAGE + 2 * AT_TILE) * 2;
        const uint32_t uVl = sb + (uint32_t)(cur * AT_STAGE + 3 * AT_TILE) * 2;

        // ---- S = Q K^T
        float s[8][4];
        #pragma unroll
        for (int nf = 0; nf < 8; nf++)
            #pragma unroll
            for (int c = 0; c < 4; c++) s[nf][c] = 0.f;

        #pragma unroll
        for (int ks = 0; ks < 4; ks++) {
            uint32_t kbh[4][4], kbl[4][4];
            const int row = ((lane >> 4) & 1) * 8 + (lane & 7);
            const int kk  = ks * 16 + ((lane >> 3) & 1) * 8;
            #pragma unroll
            for (int nb = 0; nb < 4; nb++) {
                const uint32_t off =
                    (uint32_t)(((nb * 16 + row) * AT_STRIDE + kk) * 2);
                ldsm_x4(kbh[nb], uKh + off);
                ldsm_x4(kbl[nb], uKl + off);
            }
            #pragma unroll
            for (int nf = 0; nf < 8; nf++) {
                const int nb = nf >> 1, oo = (nf & 1) * 2;
                mma16816(s[nf], qh[ks], &kbh[nb][oo]);
                mma16816(s[nf], qh[ks], &kbl[nb][oo]);
                mma16816(s[nf], ql[ks], &kbh[nb][oo]);
            }
        }

        // ---- online softmax
        float mn0 = m0, mn1 = m1;
        #pragma unroll
        for (int nf = 0; nf < 8; nf++) {
            mn0 = fmaxf(mn0, fmaxf(s[nf][0], s[nf][1]));
            mn1 = fmaxf(mn1, fmaxf(s[nf][2], s[nf][3]));
        }
        mn0 = fmaxf(mn0, __shfl_xor_sync(0xffffffffu, mn0, 1));
        mn0 = fmaxf(mn0, __shfl_xor_sync(0xffffffffu, mn0, 2));
        mn1 = fmaxf(mn1, __shfl_xor_sync(0xffffffffu, mn1, 1));
        mn1 = fmaxf(mn1, __shfl_xor_sync(0xffffffffu, mn1, 2));
        const float c0 = __expf(m0 - mn0);
        const float c1 = __expf(m1 - mn1);
        m0 = mn0; m1 = mn1;
        l0 *= c0;  l1 *= c1;
        #pragma unroll
        for (int nf = 0; nf < 8; nf++) {
            o[nf][0] *= c0; o[nf][1] *= c0;
            o[nf][2] *= c1; o[nf][3] *= c1;
        }

        // ---- P = exp(S - m), split into A-fragments
        uint32_t pah[4][4], pal[4][4];
        #pragma unroll
        for (int nf = 0; nf < 8; nf++) {
            const float p0 = __expf(s[nf][0] - m0);
            const float p1 = __expf(s[nf][1] - m0);
            const float p2 = __expf(s[nf][2] - m1);
            const float p3 = __expf(s[nf][3] - m1);
            l0 += p0 + p1;
            l1 += p2 + p3;
            __nv_bfloat16 h0 = __float2bfloat16(p0), h1 = __float2bfloat16(p1);
            __nv_bfloat16 h2 = __float2bfloat16(p2), h3 = __float2bfloat16(p3);
            const int ks = nf >> 1, base = (nf & 1) * 2;
            pah[ks][base + 0] = pack_bf16x2(p0, p1);
            pah[ks][base + 1] = pack_bf16x2(p2, p3);
            pal[ks][base + 0] = pack_bf16x2(p0 - __bfloat162float(h0),
                                            p1 - __bfloat162float(h1));
            pal[ks][base + 1] = pack_bf16x2(p2 - __bfloat162float(h2),
                                            p3 - __bfloat162float(h3));
        }

        // ---- O += P V
        #pragma unroll
        for (int ks = 0; ks < 4; ks++) {
            const int krow = ks * 16 + ((lane >> 3) & 1) * 8 + (lane & 7);
            #pragma unroll
            for (int half = 0; half < 2; half++) {
                uint32_t vbh[2][4], vbl[2][4];
                #pragma unroll
                for (int nb = 0; nb < 2; nb++) {
                    const int dh = half * 32 + nb * 16 + ((lane >> 4) & 1) * 8;
                    const uint32_t off = (uint32_t)((krow * AT_STRIDE + dh) * 2);
                    ldsm_x4_t(vbh[nb], uVh + off);
                    ldsm_x4_t(vbl[nb], uVl + off);
                }
                #pragma unroll
                for (int nf = 0; nf < 4; nf++) {
                    const int nb = nf >> 1, oo = (nf & 1) * 2;
                    mma16816(o[half * 4 + nf], pah[ks], &vbh[nb][oo]);
                    mma16816(o[half * 4 + nf], pah[ks], &vbl[nb][oo]);
                    mma16816(o[half * 4 + nf], pal[ks], &vbh[nb][oo]);
                }
            }
        }
        __syncthreads();
    }

    // ---- finalize
    l0 += __shfl_xor_sync(0xffffffffu, l0, 1);
    l0 += __shfl_xor_sync(0xffffffffu, l0, 2);
    l1 += __shfl_xor_sync(0xffffffffu, l1, 1);
    l1 += __shfl_xor_sync(0xffffffffu, l1, 2);
    const float inv0 = 1.0f / l0, inv1 = 1.0f / l1;

    const int b = bh >> 4, h = bh & 15;
    const int row0 = qbase + warp_m + (lane >> 2);
    const int ec = (lane & 3) * 2;
    #pragma unroll
    for (int nf = 0; nf < 8; nf++) {
        const int dh = nf * 8 + ec;
        split2_store(g_oh, g_ol,
                     (size_t)(b * SEQ + row0) * D_MODEL + h * 64 + dh,
                     o[nf][0] * inv0, o[nf][1] * inv0);
        split2_store(g_oh, g_ol,
                     (size_t)(b * SEQ + row0 + 8) * D_MODEL + h * 64 + dh,
                     o[nf][2] * inv1, o[nf][3] * inv1);
    }
}

// ---------------------------------------------------------------------------
extern "C" void kernel_launch(void* const* d_in, const int* in_sizes, int n_in,
                              void* d_out, int out_size)
{
    const float* x  = (const float*)d_in[0];
    const float* Wq = (const float*)d_in[1];
    const float* bq = (const float*)d_in[2];
    const float* Wk = (const float*)d_in[3];
    const float* bk = (const float*)d_in[4];
    const float* Wv = (const float*)d_in[5];
    const float* bv = (const float*)d_in[6];
    const float* Wo = (const float*)d_in[7];
    const float* bo = (const float*)d_in[8];
    float* out = (float*)d_out;

    static int attr_done = 0;
    if (!attr_done) {
        cudaFuncSetAttribute(qkv_gemm_kernel,
                             cudaFuncAttributeMaxDynamicSharedMemorySize, GEMM_SMEM_B);
        cudaFuncSetAttribute(out_gemm_kernel,
                             cudaFuncAttributeMaxDynamicSharedMemorySize, GEMM_SMEM_B);
        cudaFuncSetAttribute(attn_kernel,
                             cudaFuncAttributeMaxDynamicSharedMemorySize, ATTN_SMEM_B);
        attr_done = 1;
    }

    // device-global pointers (host side)
    __nv_bfloat16 *xh, *xl, *wqh, *wql, *wkh, *wkl, *wvh, *wvl, *woh, *wol;
    cudaGetSymbolAddress((void**)&xh,  g_xh);  cudaGetSymbolAddress((void**)&xl,  g_xl);
    cudaGetSymbolAddress((void**)&wqh, g_wqh); cudaGetSymbolAddress((void**)&wql, g_wql);
    cudaGetSymbolAddress((void**)&wkh, g_wkh); cudaGetSymbolAddress((void**)&wkl, g_wkl);
    cudaGetSymbolAddress((void**)&wvh, g_wvh); cudaGetSymbolAddress((void**)&wvl, g_wvl);
    cudaGetSymbolAddress((void**)&woh, g_woh); cudaGetSymbolAddress((void**)&wol, g_wol);

    // split passes
    split_kernel<<<1024, 256>>>(x,  xh,  xl,  M_TOTAL * D_MODEL / 4);
    split_kernel<<<256,  256>>>(Wq, wqh, wql, D_MODEL * D_MODEL / 4);
    split_kernel<<<256,  256>>>(Wk, wkh, wkl, D_MODEL * D_MODEL / 4);
    split_kernel<<<256,  256>>>(Wv, wvh, wvl, D_MODEL * D_MODEL / 4);
    split_kernel<<<256,  256>>>(Wo, woh, wol, D_MODEL * D_MODEL / 4);

    // QKV projections
    dim3 gqkv(D_MODEL / 128, M_TOTAL / 128, 3);
    qkv_gemm_kernel<<<gqkv, 256, GEMM_SMEM_B>>>(bq, bk, bv);

    // Attention
    dim3 gattn(BATCH * NUM_HEADS, SEQ / 64);
    attn_kernel<<<gattn, 128, ATTN_SMEM_B>>>();

    // Output projection
    dim3 gout(D_MODEL / 128, M_TOTAL / 128);
    out_gemm_kernel<<<gout, 256, GEMM_SMEM_B>>>(bo, out);
}

// round 15
// speedup vs baseline: 1.0010x; 1.0010x over previous
#include <cuda_runtime.h>
#include <cuda_bf16.h>
#include <cstdint>

// Problem constants
#define D_MODEL   1024
#define NUM_HEADS 16
#define HEAD_DIM  64
#define BATCH     4
#define SEQ       2048
#define M_TOTAL   (BATCH * SEQ)          // 8192 rows
#define QKV_E     (BATCH * NUM_HEADS * SEQ * HEAD_DIM)

// Pre-split bf16 scratch (allocation-free rule: __device__ globals)
__device__ __nv_bfloat16 g_xh[M_TOTAL * D_MODEL],  g_xl[M_TOTAL * D_MODEL];
__device__ __nv_bfloat16 g_wqh[D_MODEL * D_MODEL], g_wql[D_MODEL * D_MODEL];
__device__ __nv_bfloat16 g_wkh[D_MODEL * D_MODEL], g_wkl[D_MODEL * D_MODEL];
__device__ __nv_bfloat16 g_wvh[D_MODEL * D_MODEL], g_wvl[D_MODEL * D_MODEL];
__device__ __nv_bfloat16 g_woh[D_MODEL * D_MODEL], g_wol[D_MODEL * D_MODEL];
__device__ __nv_bfloat16 g_qh[QKV_E], g_ql[QKV_E];      // [B,H,S,Dh], Q pre-scaled
__device__ __nv_bfloat16 g_kh[QKV_E], g_kl[QKV_E];
__device__ __nv_bfloat16 g_vh[QKV_E], g_vl[QKV_E];
__device__ __nv_bfloat16 g_oh[M_TOTAL * D_MODEL], g_ol[M_TOTAL * D_MODEL];

// ===========================================================================
// helpers
// ===========================================================================
static __device__ __forceinline__ uint32_t smem_u32(const void* p) {
    uint32_t a;
    asm("{ .reg .u64 t; cvta.to.shared.u64 t, %1; cvt.u32.u64 %0, t; }"
        : "=r"(a) : "l"(p));
    return a;
}

static __device__ __forceinline__ void ldsm_x4(uint32_t (&r)[4], uint32_t addr) {
    asm volatile("ldmatrix.sync.aligned.m8n8.x4.shared.b16 {%0,%1,%2,%3}, [%4];"
                 : "=r"(r[0]), "=r"(r[1]), "=r"(r[2]), "=r"(r[3]) : "r"(addr));
}

static __device__ __forceinline__ void ldsm_x4_t(uint32_t (&r)[4], uint32_t addr) {
    asm volatile("ldmatrix.sync.aligned.m8n8.x4.trans.shared.b16 {%0,%1,%2,%3}, [%4];"
                 : "=r"(r[0]), "=r"(r[1]), "=r"(r[2]), "=r"(r[3]) : "r"(addr));
}

static __device__ __forceinline__ void mma16816(float (&d)[4],
                                                const uint32_t (&a)[4],
                                                const uint32_t* b)
{
    asm volatile(
        "mma.sync.aligned.m16n8k16.row.col.f32.bf16.bf16.f32 "
        "{%0,%1,%2,%3}, {%4,%5,%6,%7}, {%8,%9}, {%0,%1,%2,%3};"
        : "+f"(d[0]), "+f"(d[1]), "+f"(d[2]), "+f"(d[3])
        : "r"(a[0]), "r"(a[1]), "r"(a[2]), "r"(a[3]), "r"(b[0]), "r"(b[1]));
}

#define CP16(dst, src) \
    asm volatile("cp.async.cg.shared.global [%0], [%1], 16;" \
                 :: "r"(dst), "l"(src) : "memory")
#define CP_COMMIT() asm volatile("cp.async.commit_group;" ::: "memory")
#define CP_WAIT0()  asm volatile("cp.async.wait_group 0;" ::: "memory")
#define CP_WAIT1()  asm volatile("cp.async.wait_group 1;" ::: "memory")

static __device__ __forceinline__ uint32_t pack_bf16x2(float a, float b) {
    __nv_bfloat162 t = __floats2bfloat162_rn(a, b);
    return *reinterpret_cast<uint32_t*>(&t);
}

static __device__ __forceinline__ void split2_store(__nv_bfloat16* H, __nv_bfloat16* L,
                                                    size_t idx, float v0, float v1)
{
    __nv_bfloat16 h0 = __float2bfloat16(v0), h1 = __float2bfloat16(v1);
    *(uint32_t*)(H + idx) = pack_bf16x2(v0, v1);
    *(uint32_t*)(L + idx) = pack_bf16x2(v0 - __bfloat162float(h0),
                                        v1 - __bfloat162float(h1));
}

// ===========================================================================
// split pass: fp32 -> hi/lo bf16
// ===========================================================================
__global__ __launch_bounds__(256)
void split_kernel(const float* __restrict__ src, __nv_bfloat16* __restrict__ H,
                  __nv_bfloat16* __restrict__ L, int n4)
{
    for (int i = blockIdx.x * blockDim.x + threadIdx.x; i < n4;
         i += gridDim.x * blockDim.x) {
        float4 v = __ldg((const float4*)src + i);
        split2_store(H, L, (size_t)i * 4 + 0, v.x, v.y);
        split2_store(H, L, (size_t)i * 4 + 2, v.z, v.w);
    }
}

// ===========================================================================
// GEMM: C = (Ah+Al) @ (Bh+Bl)^T + bias   (3-term bf16 split, HMMA)
// A: [M,1024] bf16 hi/lo. B(W): [1024,1024] row-major (N x K) hi/lo.
// CTA 128x128, BK=32, double-buffered cp.async staging.
// mode 0: fp32 out [M,1024].  mode 1: split QKV out [B,H,S,Dh], val*scale.
// ===========================================================================
#define STRIDE  40                        // padded smem row (bf16 elems), 80B
#define TILE_E  (128 * STRIDE)            // 5120 elems per tile
#define STAGE_E (4 * TILE_E)              // Ah,Al,Bh,Bl
#define GEMM_SMEM_B (2 * STAGE_E * 2)     // bytes = 81920

extern __shared__ __nv_bfloat16 dsm[];

static __device__ __forceinline__ void gemm_issue(const __nv_bfloat16* Ah,
                                                  const __nv_bfloat16* Al,
                                                  const __nv_bfloat16* Bh,
                                                  const __nv_bfloat16* Bl,
                                                  uint32_t sb, int stage,
                                                  int bm, int bn, int k0, int tid)
{
    const uint32_t base = sb + (uint32_t)(stage * STAGE_E) * 2;
    #pragma unroll
    for (int i = 0; i < 2; i++) {
        const int idx = tid + i * 256;          // 0..511
        const int row = idx >> 2, c = idx & 3;  // row 0..127, 16B chunk 0..3
        const size_t gofs = (size_t)row * D_MODEL + k0 + c * 8;
        const uint32_t sofs = (uint32_t)(row * STRIDE + c * 8) * 2;
        CP16(base + 0 * TILE_E * 2 + sofs, Ah + (size_t)bm * D_MODEL + gofs);
        CP16(base + 1 * TILE_E * 2 + sofs, Al + (size_t)bm * D_MODEL + gofs);
        CP16(base + 2 * TILE_E * 2 + sofs, Bh + (size_t)bn * D_MODEL + gofs);
        CP16(base + 3 * TILE_E * 2 + sofs, Bl + (size_t)bn * D_MODEL + gofs);
    }
}

static __device__ __forceinline__ void gemm_tc_body(const __nv_bfloat16* __restrict__ Ah,
                                                    const __nv_bfloat16* __restrict__ Al,
                                                    const __nv_bfloat16* __restrict__ Bh,
                                                    const __nv_bfloat16* __restrict__ Bl,
                                                    const float* __restrict__ bias,
                                                    float* __restrict__ Cf,
                                                    __nv_bfloat16* __restrict__ Ch,
                                                    __nv_bfloat16* __restrict__ Cl,
                                                    int mode, float scale)
{
    const uint32_t sb = smem_u32(dsm);
    const int tid  = threadIdx.x;
    const int wid  = tid >> 5;
    const int lane = tid & 31;
    const int bm = blockIdx.y * 128;
    const int bn = blockIdx.x * 128;
    const int warp_m = (wid & 1) * 64;
    const int warp_n = (wid >> 1) * 32;

    float acc[4][4][4];
    #pragma unroll
    for (int i = 0; i < 4; i++)
        #pragma unroll
        for (int j = 0; j < 4; j++)
            #pragma unroll
            for (int c = 0; c < 4; c++) acc[i][j][c] = 0.f;

    gemm_issue(Ah, Al, Bh, Bl, sb, 0, bm, bn, 0, tid);
    CP_COMMIT();

    #pragma unroll 1
    for (int chunk = 0; chunk < D_MODEL / 32; chunk++) {
        const int cur = chunk & 1;
        if (chunk + 1 < D_MODEL / 32) {
            gemm_issue(Ah, Al, Bh, Bl, sb, cur ^ 1, bm, bn, (chunk + 1) * 32, tid);
            CP_COMMIT();
            CP_WAIT1();
        } else {
            CP_WAIT0();
        }
        __syncthreads();

        const uint32_t uAh = sb + (uint32_t)(cur * STAGE_E + 0 * TILE_E) * 2;
        const uint32_t uAl = sb + (uint32_t)(cur * STAGE_E + 1 * TILE_E) * 2;
        const uint32_t uBh = sb + (uint32_t)(cur * STAGE_E + 2 * TILE_E) * 2;
        const uint32_t uBl = sb + (uint32_t)(cur * STAGE_E + 3 * TILE_E) * 2;

        #pragma unroll
        for (int ks = 0; ks < 2; ks++) {
            uint32_t ah[4][4], al[4][4];
            {
                const int row = ((lane >> 3) & 1) * 8 + (lane & 7);
                const int kk  = ks * 16 + ((lane >> 4) & 1) * 8;
                #pragma unroll
                for (int mf = 0; mf < 4; mf++) {
                    const uint32_t off =
                        (uint32_t)(((warp_m + mf * 16 + row) * STRIDE + kk) * 2);
                    ldsm_x4(ah[mf], uAh + off);
                    ldsm_x4(al[mf], uAl + off);
                }
            }
            uint32_t bh[2][4], bl[2][4];
            {
                const int row = ((lane >> 4) & 1) * 8 + (lane & 7);
                const int kk  = ks * 16 + ((lane >> 3) & 1) * 8;
                #pragma unroll
                for (int nb = 0; nb < 2; nb++) {
                    const uint32_t off =
                        (uint32_t)(((warp_n + nb * 16 + row) * STRIDE + kk) * 2);
                    ldsm_x4(bh[nb], uBh + off);
                    ldsm_x4(bl[nb], uBl + off);
                }
            }
            #pragma unroll
            for (int mf = 0; mf < 4; mf++)
                #pragma unroll
                for (int nf = 0; nf < 4; nf++) {
                    const int nb = nf >> 1, o = (nf & 1) * 2;
                    mma16816(acc[mf][nf], ah[mf], &bh[nb][o]);
                    mma16816(acc[mf][nf], ah[mf], &bl[nb][o]);
                    mma16816(acc[mf][nf], al[mf], &bh[nb][o]);
                }
        }
        __syncthreads();
    }

    const int er = lane >> 2;
    const int ec = (lane & 3) * 2;
    #pragma unroll
    for (int mf = 0; mf < 4; mf++) {
        #pragma unroll
        for (int nf = 0; nf < 4; nf++) {
            const int n = bn + warp_n + nf * 8 + ec;
            const float b0 = __ldg(bias + n), b1 = __ldg(bias + n + 1);
            #pragma unroll
            for (int half = 0; half < 2; half++) {
                const int m = bm + warp_m + mf * 16 + er + half * 8;
                const float v0 = (acc[mf][nf][half * 2 + 0] + b0) * scale;
                const float v1 = (acc[mf][nf][half * 2 + 1] + b1) * scale;
                if (mode == 0) {
                    float2 r; r.x = v0; r.y = v1;
                    *(float2*)(Cf + (size_t)m * D_MODEL + n) = r;
                } else {
                    const int bb = m >> 11, s = m & 2047;
                    const int h = n >> 6,  d = n & 63;
                    const size_t idx =
                        (((size_t)(bb * NUM_HEADS + h) * SEQ + s) << 6) + d;
                    split2_store(Ch, Cl, idx, v0, v1);
                }
            }
        }
    }
}

__global__ __launch_bounds__(256)
void qkv_gemm_kernel(const float* __restrict__ bq, const float* __restrict__ bk,
                     const float* __restrict__ bv)
{
    if (blockIdx.z == 0)
        gemm_tc_body(g_xh, g_xl, g_wqh, g_wql, bq, nullptr, g_qh, g_ql, 1, 0.125f);
    else if (blockIdx.z == 1)
        gemm_tc_body(g_xh, g_xl, g_wkh, g_wkl, bk, nullptr, g_kh, g_kl, 1, 1.0f);
    else
        gemm_tc_body(g_xh, g_xl, g_wvh, g_wvl, bv, nullptr, g_vh, g_vl, 1, 1.0f);
}

__global__ __launch_bounds__(256)
void out_gemm_kernel(const float* __restrict__ bo, float* __restrict__ out)
{
    gemm_tc_body(g_oh, g_ol, g_woh, g_wol, bo, out, nullptr, nullptr, 0, 1.0f);
}

// ===========================================================================
// Tensor-core flash attention, pre-split inputs, cp.async double-buffered.
// CTA: 64 q-rows, 4 warps. K/V tiles of 64 keys.
// ===========================================================================
#define AT_STRIDE 72                       // bf16 elems per row (144B, 16B mult)
#define AT_TILE   (64 * AT_STRIDE)         // 4608 elems
#define AT_STAGE  (4 * AT_TILE)            // Kh,Kl,Vh,Vl
#define ATTN_SMEM_B (2 * AT_STAGE * 2)     // 73728 bytes

static __device__ __forceinline__ void attn_issue(uint32_t sb, int stage,
                                                  size_t kvbase, int kt, int tid)
{
    const uint32_t base = sb + (uint32_t)(stage * AT_STAGE) * 2;
    const __nv_bfloat16* srcs[4] = { g_kh, g_kl, g_vh, g_vl };
    #pragma unroll
    for (int i = 0; i < 16; i++) {
        const int idx = tid + i * 128;             // 0..2047
        const int arr = idx >> 9;                  // 0..3
        const int j   = idx & 511;
        const int row = j >> 3, c = j & 7;
        const __nv_bfloat16* src =
            srcs[arr] + kvbase + (size_t)(kt * 64 + row) * HEAD_DIM + c * 8;
        const uint32_t dst =
            base + (uint32_t)(arr * AT_TILE + row * AT_STRIDE + c * 8) * 2;
        CP16(dst, src);
    }
}

__global__ __launch_bounds__(128)
void attn_kernel()
{
    const uint32_t sb = smem_u32(dsm);

    const int bh    = blockIdx.x;            // b*16 + h
    const int qbase = blockIdx.y * 64;
    const int tid   = threadIdx.x;
    const int wid   = tid >> 5;
    const int lane  = tid & 31;
    const int warp_m = wid * 16;

    const size_t kvbase = (size_t)bh * SEQ * HEAD_DIM;

    // ---- stage Q (already scaled+split) into stage-0 Kh/Kl area
    #pragma unroll
    for (int i = 0; i < 8; i++) {
        const int idx = tid + i * 128;           // 0..1023
        const int arr = idx >> 9;                // 0: hi, 1: lo
        const int j   = idx & 511;
        const int row = j >> 3, c = j & 7;
        const __nv_bfloat16* src =
            (arr == 0 ? g_qh : g_ql) + kvbase + (size_t)(qbase + row) * HEAD_DIM + c * 8;
        const uint32_t dst = sb + (uint32_t)(arr * AT_TILE + row * AT_STRIDE + c * 8) * 2;
        CP16(dst, src);
    }
    CP_COMMIT();
    CP_WAIT0();
    __syncthreads();

    uint32_t qh[4][4], ql[4][4];
    {
        const int row = warp_m + ((lane >> 3) & 1) * 8 + (lane & 7);
        #pragma unroll
        for (int ks = 0; ks < 4; ks++) {
            const int kk = ks * 16 + ((lane >> 4) & 1) * 8;
            const uint32_t off = (uint32_t)((row * AT_STRIDE + kk) * 2);
            ldsm_x4(qh[ks], sb + off);
            ldsm_x4(ql[ks], sb + (uint32_t)(AT_TILE * 2) + off);
        }
    }
    __syncthreads();

    float o[8][4];
    #pragma unroll
    for (int nf = 0; nf < 8; nf++)
        #pragma unroll
        for (int c = 0; c < 4; c++) o[nf][c] = 0.f;
    float m0 = -1e30f, m1 = -1e30f, l0 = 0.f, l1 = 0.f;

    attn_issue(sb, 0, kvbase, 0, tid);
    CP_COMMIT();

    #pragma unroll 1
    for (int kt = 0; kt < SEQ / 64; kt++) {
        const int cur = kt & 1;
        if (kt + 1 < SEQ / 64) {
            attn_issue(sb, cur ^ 1, kvbase, kt + 1, tid);
            CP_COMMIT();
            CP_WAIT1();
        } else {
            CP_WAIT0();
        }
        __syncthreads();

        const uint32_t uKh = sb + (uint32_t)(cur * AT_STAGE + 0 * AT_TILE) * 2;
        const uint32_t uKl = sb + (uint32_t)(cur * AT_STAGE + 1 * AT_TILE) * 2;
        const uint32_t uVh = sb + (uint32_t)(cur * AT_STAGE + 2 * AT_TILE) * 2;
        const uint32_t uVl = sb + (uint32_t)(cur * AT_STAGE + 3 * AT_TILE) * 2;

        // ---- S = Q K^T
        float s[8][4];
        #pragma unroll
        for (int nf = 0; nf < 8; nf++)
            #pragma unroll
            for (int c = 0; c < 4; c++) s[nf][c] = 0.f;

        #pragma unroll
        for (int ks = 0; ks < 4; ks++) {
            uint32_t kbh[4][4], kbl[4][4];
            const int row = ((lane >> 4) & 1) * 8 + (lane & 7);
            const int kk  = ks * 16 + ((lane >> 3) & 1) * 8;
            #pragma unroll
            for (int nb = 0; nb < 4; nb++) {
                const uint32_t off =
                    (uint32_t)(((nb * 16 + row) * AT_STRIDE + kk) * 2);
                ldsm_x4(kbh[nb], uKh + off);
                ldsm_x4(kbl[nb], uKl + off);
            }
            #pragma unroll
            for (int nf = 0; nf < 8; nf++) {
                const int nb = nf >> 1, oo = (nf & 1) * 2;
                mma16816(s[nf], qh[ks], &kbh[nb][oo]);
                mma16816(s[nf], qh[ks], &kbl[nb][oo]);
                mma16816(s[nf], ql[ks], &kbh[nb][oo]);
            }
        }

        // ---- online softmax
        float mn0 = m0, mn1 = m1;
        #pragma unroll
        for (int nf = 0; nf < 8; nf++) {
            mn0 = fmaxf(mn0, fmaxf(s[nf][0], s[nf][1]));
            mn1 = fmaxf(mn1, fmaxf(s[nf][2], s[nf][3]));
        }
        mn0 = fmaxf(mn0, __shfl_xor_sync(0xffffffffu, mn0, 1));
        mn0 = fmaxf(mn0, __shfl_xor_sync(0xffffffffu, mn0, 2));
        mn1 = fmaxf(mn1, __shfl_xor_sync(0xffffffffu, mn1, 1));
        mn1 = fmaxf(mn1, __shfl_xor_sync(0xffffffffu, mn1, 2));
        const float c0 = __expf(m0 - mn0);
        const float c1 = __expf(m1 - mn1);
        m0 = mn0; m1 = mn1;
        l0 *= c0;  l1 *= c1;
        #pragma unroll
        for (int nf = 0; nf < 8; nf++) {
            o[nf][0] *= c0; o[nf][1] *= c0;
            o[nf][2] *= c1; o[nf][3] *= c1;
        }

        // ---- P = exp(S - m), split into A-fragments
        uint32_t pah[4][4], pal[4][4];
        #pragma unroll
        for (int nf = 0; nf < 8; nf++) {
            const float p0 = __expf(s[nf][0] - m0);
            const float p1 = __expf(s[nf][1] - m0);
            const float p2 = __expf(s[nf][2] - m1);
            const float p3 = __expf(s[nf][3] - m1);
            l0 += p0 + p1;
            l1 += p2 + p3;
            __nv_bfloat16 h0 = __float2bfloat16(p0), h1 = __float2bfloat16(p1);
            __nv_bfloat16 h2 = __float2bfloat16(p2), h3 = __float2bfloat16(p3);
            const int ks = nf >> 1, base = (nf & 1) * 2;
            pah[ks][base + 0] = pack_bf16x2(p0, p1);
            pah[ks][base + 1] = pack_bf16x2(p2, p3);
            pal[ks][base + 0] = pack_bf16x2(p0 - __bfloat162float(h0),
                                            p1 - __bfloat162float(h1));
            pal[ks][base + 1] = pack_bf16x2(p2 - __bfloat162float(h2),
                                            p3 - __bfloat162float(h3));
        }

        // ---- O += P V
        #pragma unroll
        for (int ks = 0; ks < 4; ks++) {
            const int krow = ks * 16 + ((lane >> 3) & 1) * 8 + (lane & 7);
            #pragma unroll
            for (int half = 0; half < 2; half++) {
                uint32_t vbh[2][4], vbl[2][4];
                #pragma unroll
                for (int nb = 0; nb < 2; nb++) {
                    const int dh = half * 32 + nb * 16 + ((lane >> 4) & 1) * 8;
                    const uint32_t off = (uint32_t)((krow * AT_STRIDE + dh) * 2);
                    ldsm_x4_t(vbh[nb], uVh + off);
                    ldsm_x4_t(vbl[nb], uVl + off);
                }
                #pragma unroll
                for (int nf = 0; nf < 4; nf++) {
                    const int nb = nf >> 1, oo = (nf & 1) * 2;
                    mma16816(o[half * 4 + nf], pah[ks], &vbh[nb][oo]);
                    mma16816(o[half * 4 + nf], pah[ks], &vbl[nb][oo]);
                    mma16816(o[half * 4 + nf], pal[ks], &vbh[nb][oo]);
                }
            }
        }
        __syncthreads();
    }

    // ---- finalize
    l0 += __shfl_xor_sync(0xffffffffu, l0, 1);
    l0 += __shfl_xor_sync(0xffffffffu, l0, 2);
    l1 += __shfl_xor_sync(0xffffffffu, l1, 1);
    l1 += __shfl_xor_sync(0xffffffffu, l1, 2);
    const float inv0 = 1.0f / l0, inv1 = 1.0f / l1;

    const int b = bh >> 4, h = bh & 15;
    const int row0 = qbase + warp_m + (lane >> 2);
    const int ec = (lane & 3) * 2;
    #pragma unroll
    for (int nf = 0; nf < 8; nf++) {
        const int dh = nf * 8 + ec;
        split2_store(g_oh, g_ol,
                     (size_t)(b * SEQ + row0) * D_MODEL + h * 64 + dh,
                     o[nf][0] * inv0, o[nf][1] * inv0);
        split2_store(g_oh, g_ol,
                     (size_t)(b * SEQ + row0 + 8) * D_MODEL + h * 64 + dh,
                     o[nf][2] * inv1, o[nf][3] * inv1);
    }
}

// ---------------------------------------------------------------------------
extern "C" void kernel_launch(void* const* d_in, const int* in_sizes, int n_in,
                              void* d_out, int out_size)
{
    const float* x  = (const float*)d_in[0];
    const float* Wq = (const float*)d_in[1];
    const float* bq = (const float*)d_in[2];
    const float* Wk = (const float*)d_in[3];
    const float* bk = (const float*)d_in[4];
    const float* Wv = (const float*)d_in[5];
    const float* bv = (const float*)d_in[6];
    const float* Wo = (const float*)d_in[7];
    const float* bo = (const float*)d_in[8];
    float* out = (float*)d_out;

    static int attr_done = 0;
    if (!attr_done) {
        cudaFuncSetAttribute(qkv_gemm_kernel,
                             cudaFuncAttributeMaxDynamicSharedMemorySize, GEMM_SMEM_B);
        cudaFuncSetAttribute(out_gemm_kernel,
                             cudaFuncAttributeMaxDynamicSharedMemorySize, GEMM_SMEM_B);
        cudaFuncSetAttribute(attn_kernel,
                             cudaFuncAttributeMaxDynamicSharedMemorySize, ATTN_SMEM_B);
        attr_done = 1;
    }

    // device-global pointers (host side)
    __nv_bfloat16 *xh, *xl, *wqh, *wql, *wkh, *wkl, *wvh, *wvl, *woh, *wol;
    cudaGetSymbolAddress((void**)&xh,  g_xh);  cudaGetSymbolAddress((void**)&xl,  g_xl);
    cudaGetSymbolAddress((void**)&wqh, g_wqh); cudaGetSymbolAddress((void**)&wql, g_wql);
    cudaGetSymbolAddress((void**)&wkh, g_wkh); cudaGetSymbolAddress((void**)&wkl, g_wkl);
    cudaGetSymbolAddress((void**)&wvh, g_wvh); cudaGetSymbolAddress((void**)&wvl, g_wvl);
    cudaGetSymbolAddress((void**)&woh, g_woh); cudaGetSymbolAddress((void**)&wol, g_wol);

    // split passes
    split_kernel<<<1024, 256>>>(x,  xh,  xl,  M_TOTAL * D_MODEL / 4);
    split_kernel<<<256,  256>>>(Wq, wqh, wql, D_MODEL * D_MODEL / 4);
    split_kernel<<<256,  256>>>(Wk, wkh, wkl, D_MODEL * D_MODEL / 4);
    split_kernel<<<256,  256>>>(Wv, wvh, wvl, D_MODEL * D_MODEL / 4);
    split_kernel<<<256,  256>>>(Wo, woh, wol, D_MODEL * D_MODEL / 4);

    // QKV projections
    dim3 gqkv(D_MODEL / 128, M_TOTAL / 128, 3);
    qkv_gemm_kernel<<<gqkv, 256, GEMM_SMEM_B>>>(bq, bk, bv);

    // Attention
    dim3 gattn(BATCH * NUM_HEADS, SEQ / 64);
    attn_kernel<<<gattn, 128, ATTN_SMEM_B>>>();

    // Output projection
    dim3 gout(D_MODEL / 128, M_TOTAL / 128);
    out_gemm_kernel<<<gout, 256, GEMM_SMEM_B>>>(bo, out);
}

// round 16
// speedup vs baseline: 1.0018x; 1.0008x over previous
#include <cuda_runtime.h>
#include <cuda_bf16.h>
#include <cstdint>

// Problem constants
#define D_MODEL   1024
#define NUM_HEADS 16
#define HEAD_DIM  64
#define BATCH     4
#define SEQ       2048
#define M_TOTAL   (BATCH * SEQ)          // 8192 rows
#define QKV_E     (BATCH * NUM_HEADS * SEQ * HEAD_DIM)

// Pre-split bf16 scratch (allocation-free rule: __device__ globals)
__device__ __nv_bfloat16 g_xh[M_TOTAL * D_MODEL],  g_xl[M_TOTAL * D_MODEL];
__device__ __nv_bfloat16 g_wqh[D_MODEL * D_MODEL], g_wql[D_MODEL * D_MODEL];
__device__ __nv_bfloat16 g_wkh[D_MODEL * D_MODEL], g_wkl[D_MODEL * D_MODEL];
__device__ __nv_bfloat16 g_wvh[D_MODEL * D_MODEL], g_wvl[D_MODEL * D_MODEL];
__device__ __nv_bfloat16 g_woh[D_MODEL * D_MODEL], g_wol[D_MODEL * D_MODEL];
__device__ __nv_bfloat16 g_qh[QKV_E], g_ql[QKV_E];      // [B,H,S,Dh], Q pre-scaled
__device__ __nv_bfloat16 g_kh[QKV_E], g_kl[QKV_E];
__device__ __nv_bfloat16 g_vh[QKV_E], g_vl[QKV_E];
__device__ __nv_bfloat16 g_oh[M_TOTAL * D_MODEL], g_ol[M_TOTAL * D_MODEL];

// ===========================================================================
// helpers
// ===========================================================================
static __device__ __forceinline__ uint32_t smem_u32(const void* p) {
    uint32_t a;
    asm("{ .reg .u64 t; cvta.to.shared.u64 t, %1; cvt.u32.u64 %0, t; }"
        : "=r"(a) : "l"(p));
    return a;
}

static __device__ __forceinline__ void ldsm_x4(uint32_t (&r)[4], uint32_t addr) {
    asm volatile("ldmatrix.sync.aligned.m8n8.x4.shared.b16 {%0,%1,%2,%3}, [%4];"
                 : "=r"(r[0]), "=r"(r[1]), "=r"(r[2]), "=r"(r[3]) : "r"(addr));
}

static __device__ __forceinline__ void ldsm_x4_t(uint32_t (&r)[4], uint32_t addr) {
    asm volatile("ldmatrix.sync.aligned.m8n8.x4.trans.shared.b16 {%0,%1,%2,%3}, [%4];"
                 : "=r"(r[0]), "=r"(r[1]), "=r"(r[2]), "=r"(r[3]) : "r"(addr));
}

static __device__ __forceinline__ void mma16816(float (&d)[4],
                                                const uint32_t (&a)[4],
                                                const uint32_t* b)
{
    asm volatile(
        "mma.sync.aligned.m16n8k16.row.col.f32.bf16.bf16.f32 "
        "{%0,%1,%2,%3}, {%4,%5,%6,%7}, {%8,%9}, {%0,%1,%2,%3};"
        : "+f"(d[0]), "+f"(d[1]), "+f"(d[2]), "+f"(d[3])
        : "r"(a[0]), "r"(a[1]), "r"(a[2]), "r"(a[3]), "r"(b[0]), "r"(b[1]));
}

#define CP16(dst, src) \
    asm volatile("cp.async.cg.shared.global [%0], [%1], 16;" \
                 :: "r"(dst), "l"(src) : "memory")
#define CP_COMMIT() asm volatile("cp.async.commit_group;" ::: "memory")
#define CP_WAIT0()  asm volatile("cp.async.wait_group 0;" ::: "memory")
#define CP_WAIT1()  asm volatile("cp.async.wait_group 1;" ::: "memory")

static __device__ __forceinline__ uint32_t pack_bf16x2(float a, float b) {
    __nv_bfloat162 t = __floats2bfloat162_rn(a, b);
    return *reinterpret_cast<uint32_t*>(&t);
}

static __device__ __forceinline__ void split2_store(__nv_bfloat16* H, __nv_bfloat16* L,
                                                    size_t idx, float v0, float v1)
{
    __nv_bfloat16 h0 = __float2bfloat16(v0), h1 = __float2bfloat16(v1);
    *(uint32_t*)(H + idx) = pack_bf16x2(v0, v1);
    *(uint32_t*)(L + idx) = pack_bf16x2(v0 - __bfloat162float(h0),
                                        v1 - __bfloat162float(h1));
}

// ===========================================================================
// split pass: fp32 -> hi/lo bf16
// ===========================================================================
__global__ __launch_bounds__(256)
void split_kernel(const float* __restrict__ src, __nv_bfloat16* __restrict__ H,
                  __nv_bfloat16* __restrict__ L, int n4)
{
    for (int i = blockIdx.x * blockDim.x + threadIdx.x; i < n4;
         i += gridDim.x * blockDim.x) {
        float4 v = __ldg((const float4*)src + i);
        split2_store(H, L, (size_t)i * 4 + 0, v.x, v.y);
        split2_store(H, L, (size_t)i * 4 + 2, v.z, v.w);
    }
}

// ===========================================================================
// GEMM: C = (Ah+Al) @ (Bh+Bl)^T + bias   (3-term bf16 split, HMMA)
// A: [M,1024] bf16 hi/lo. B(W): [1024,1024] row-major (N x K) hi/lo.
// CTA 128x128, BK=32, double-buffered cp.async staging.
// mode 0: fp32 out [M,1024].  mode 1: split QKV out [B,H,S,Dh], val*scale.
// ===========================================================================
#define STRIDE  40                        // padded smem row (bf16 elems), 80B
#define TILE_E  (128 * STRIDE)            // 5120 elems per tile
#define STAGE_E (4 * TILE_E)              // Ah,Al,Bh,Bl
#define GEMM_SMEM_B (2 * STAGE_E * 2)     // bytes = 81920

extern __shared__ __nv_bfloat16 dsm[];

static __device__ __forceinline__ void gemm_issue(const __nv_bfloat16* Ah,
                                                  const __nv_bfloat16* Al,
                                                  const __nv_bfloat16* Bh,
                                                  const __nv_bfloat16* Bl,
                                                  uint32_t sb, int stage,
                                                  int bm, int bn, int k0, int tid)
{
    const uint32_t base = sb + (uint32_t)(stage * STAGE_E) * 2;
    #pragma unroll
    for (int i = 0; i < 2; i++) {
        const int idx = tid + i * 256;          // 0..511
        const int row = idx >> 2, c = idx & 3;  // row 0..127, 16B chunk 0..3
        const size_t gofs = (size_t)row * D_MODEL + k0 + c * 8;
        const uint32_t sofs = (uint32_t)(row * STRIDE + c * 8) * 2;
        CP16(base + 0 * TILE_E * 2 + sofs, Ah + (size_t)bm * D_MODEL + gofs);
        CP16(base + 1 * TILE_E * 2 + sofs, Al + (size_t)bm * D_MODEL + gofs);
        CP16(base + 2 * TILE_E * 2 + sofs, Bh + (size_t)bn * D_MODEL + gofs);
        CP16(base + 3 * TILE_E * 2 + sofs, Bl + (size_t)bn * D_MODEL + gofs);
    }
}

static __device__ __forceinline__ void gemm_tc_body(const __nv_bfloat16* __restrict__ Ah,
                                                    const __nv_bfloat16* __restrict__ Al,
                                                    const __nv_bfloat16* __restrict__ Bh,
                                                    const __nv_bfloat16* __restrict__ Bl,
                                                    const float* __restrict__ bias,
                                                    float* __restrict__ Cf,
                                                    __nv_bfloat16* __restrict__ Ch,
                                                    __nv_bfloat16* __restrict__ Cl,
                                                    int mode, float scale)
{
    const uint32_t sb = smem_u32(dsm);
    const int tid  = threadIdx.x;
    const int wid  = tid >> 5;
    const int lane = tid & 31;
    const int bm = blockIdx.y * 128;
    const int bn = blockIdx.x * 128;
    const int warp_m = (wid & 1) * 64;
    const int warp_n = (wid >> 1) * 32;

    float acc[4][4][4];
    #pragma unroll
    for (int i = 0; i < 4; i++)
        #pragma unroll
        for (int j = 0; j < 4; j++)
            #pragma unroll
            for (int c = 0; c < 4; c++) acc[i][j][c] = 0.f;

    gemm_issue(Ah, Al, Bh, Bl, sb, 0, bm, bn, 0, tid);
    CP_COMMIT();

    #pragma unroll 1
    for (int chunk = 0; chunk < D_MODEL / 32; chunk++) {
        const int cur = chunk & 1;
        if (chunk + 1 < D_MODEL / 32) {
            gemm_issue(Ah, Al, Bh, Bl, sb, cur ^ 1, bm, bn, (chunk + 1) * 32, tid);
            CP_COMMIT();
            CP_WAIT1();
        } else {
            CP_WAIT0();
        }
        __syncthreads();

        const uint32_t uAh = sb + (uint32_t)(cur * STAGE_E + 0 * TILE_E) * 2;
        const uint32_t uAl = sb + (uint32_t)(cur * STAGE_E + 1 * TILE_E) * 2;
        const uint32_t uBh = sb + (uint32_t)(cur * STAGE_E + 2 * TILE_E) * 2;
        const uint32_t uBl = sb + (uint32_t)(cur * STAGE_E + 3 * TILE_E) * 2;

        #pragma unroll
        for (int ks = 0; ks < 2; ks++) {
            uint32_t ah[4][4], al[4][4];
            {
                const int row = ((lane >> 3) & 1) * 8 + (lane & 7);
                const int kk  = ks * 16 + ((lane >> 4) & 1) * 8;
                #pragma unroll
                for (int mf = 0; mf < 4; mf++) {
                    const uint32_t off =
                        (uint32_t)(((warp_m + mf * 16 + row) * STRIDE + kk) * 2);
                    ldsm_x4(ah[mf], uAh + off);
                    ldsm_x4(al[mf], uAl + off);
                }
            }
            uint32_t bh[2][4], bl[2][4];
            {
                const int row = ((lane >> 4) & 1) * 8 + (lane & 7);
                const int kk  = ks * 16 + ((lane >> 3) & 1) * 8;
                #pragma unroll
                for (int nb = 0; nb < 2; nb++) {
                    const uint32_t off =
                        (uint32_t)(((warp_n + nb * 16 + row) * STRIDE + kk) * 2);
                    ldsm_x4(bh[nb], uBh + off);
                    ldsm_x4(bl[nb], uBl + off);
                }
            }
            #pragma unroll
            for (int mf = 0; mf < 4; mf++)
                #pragma unroll
                for (int nf = 0; nf < 4; nf++) {
                    const int nb = nf >> 1, o = (nf & 1) * 2;
                    mma16816(acc[mf][nf], ah[mf], &bh[nb][o]);
                    mma16816(acc[mf][nf], ah[mf], &bl[nb][o]);
                    mma16816(acc[mf][nf], al[mf], &bh[nb][o]);
                }
        }
        __syncthreads();
    }

    const int er = lane >> 2;
    const int ec = (lane & 3) * 2;
    #pragma unroll
    for (int mf = 0; mf < 4; mf++) {
        #pragma unroll
        for (int nf = 0; nf < 4; nf++) {
            const int n = bn + warp_n + nf * 8 + ec;
            const float b0 = __ldg(bias + n), b1 = __ldg(bias + n + 1);
            #pragma unroll
            for (int half = 0; half < 2; half++) {
                const int m = bm + warp_m + mf * 16 + er + half * 8;
                const float v0 = (acc[mf][nf][half * 2 + 0] + b0) * scale;
                const float v1 = (acc[mf][nf][half * 2 + 1] + b1) * scale;
                if (mode == 0) {
                    float2 r; r.x = v0; r.y = v1;
                    *(float2*)(Cf + (size_t)m * D_MODEL + n) = r;
                } else {
                    const int bb = m >> 11, s = m & 2047;
                    const int h = n >> 6,  d = n & 63;
                    const size_t idx =
                        (((size_t)(bb * NUM_HEADS + h) * SEQ + s) << 6) + d;
                    split2_store(Ch, Cl, idx, v0, v1);
                }
            }
        }
    }
}

__global__ __launch_bounds__(256)
void qkv_gemm_kernel(const float* __restrict__ bq, const float* __restrict__ bk,
                     const float* __restrict__ bv)
{
    if (blockIdx.z == 0)
        gemm_tc_body(g_xh, g_xl, g_wqh, g_wql, bq, nullptr, g_qh, g_ql, 1, 0.125f);
    else if (blockIdx.z == 1)
        gemm_tc_body(g_xh, g_xl, g_wkh, g_wkl, bk, nullptr, g_kh, g_kl, 1, 1.0f);
    else
        gemm_tc_body(g_xh, g_xl, g_wvh, g_wvl, bv, nullptr, g_vh, g_vl, 1, 1.0f);
}

__global__ __launch_bounds__(256)
void out_gemm_kernel(const float* __restrict__ bo, float* __restrict__ out)
{
    gemm_tc_body(g_oh, g_ol, g_woh, g_wol, bo, out, nullptr, nullptr, 0, 1.0f);
}

// ===========================================================================
// Tensor-core flash attention, pre-split inputs, cp.async double-buffered.
// CTA: 64 q-rows, 4 warps. K/V tiles of 64 keys.
// ===========================================================================
#define AT_STRIDE 72                       // bf16 elems per row (144B, 16B mult)
#define AT_TILE   (64 * AT_STRIDE)         // 4608 elems
#define AT_STAGE  (4 * AT_TILE)            // Kh,Kl,Vh,Vl
#define ATTN_SMEM_B (2 * AT_STAGE * 2)     // 73728 bytes

static __device__ __forceinline__ void attn_issue(uint32_t sb, int stage,
                                                  size_t kvbase, int kt, int tid)
{
    const uint32_t base = sb + (uint32_t)(stage * AT_STAGE) * 2;
    const __nv_bfloat16* srcs[4] = { g_kh, g_kl, g_vh, g_vl };
    #pragma unroll
    for (int i = 0; i < 16; i++) {
        const int idx = tid + i * 128;             // 0..2047
        const int arr = idx >> 9;                  // 0..3
        const int j   = idx & 511;
        const int row = j >> 3, c = j & 7;
        const __nv_bfloat16* src =
            srcs[arr] + kvbase + (size_t)(kt * 64 + row) * HEAD_DIM + c * 8;
        const uint32_t dst =
            base + (uint32_t)(arr * AT_TILE + row * AT_STRIDE + c * 8) * 2;
        CP16(dst, src);
    }
}

__global__ __launch_bounds__(128)
void attn_kernel()
{
    const uint32_t sb = smem_u32(dsm);

    const int bh    = blockIdx.x;            // b*16 + h
    const int qbase = blockIdx.y * 64;
    const int tid   = threadIdx.x;
    const int wid   = tid >> 5;
    const int lane  = tid & 31;
    const int warp_m = wid * 16;

    const size_t kvbase = (size_t)bh * SEQ * HEAD_DIM;

    // ---- stage Q (already scaled+split) into stage-0 Kh/Kl area
    #pragma unroll
    for (int i = 0; i < 8; i++) {
        const int idx = tid + i * 128;           // 0..1023
        const int arr = idx >> 9;                // 0: hi, 1: lo
        const int j   = idx & 511;
        const int row = j >> 3, c = j & 7;
        const __nv_bfloat16* src =
            (arr == 0 ? g_qh : g_ql) + kvbase + (size_t)(qbase + row) * HEAD_DIM + c * 8;
        const uint32_t dst = sb + (uint32_t)(arr * AT_TILE + row * AT_STRIDE + c * 8) * 2;
        CP16(dst, src);
    }
    CP_COMMIT();
    CP_WAIT0();
    __syncthreads();

    uint32_t qh[4][4], ql[4][4];
    {
        const int row = warp_m + ((lane >> 3) & 1) * 8 + (lane & 7);
        #pragma unroll
        for (int ks = 0; ks < 4; ks++) {
            const int kk = ks * 16 + ((lane >> 4) & 1) * 8;
            const uint32_t off = (uint32_t)((row * AT_STRIDE + kk) * 2);
            ldsm_x4(qh[ks], sb + off);
            ldsm_x4(ql[ks], sb + (uint32_t)(AT_TILE * 2) + off);
        }
    }
    __syncthreads();

    float o[8][4];
    #pragma unroll
    for (int nf = 0; nf < 8; nf++)
        #pragma unroll
        for (int c = 0; c < 4; c++) o[nf][c] = 0.f;
    float m0 = -1e30f, m1 = -1e30f, l0 = 0.f, l1 = 0.f;

    attn_issue(sb, 0, kvbase, 0, tid);
    CP_COMMIT();

    #pragma unroll 1
    for (int kt = 0; kt < SEQ / 64; kt++) {
        const int cur = kt & 1;
        if (kt + 1 < SEQ / 64) {
            attn_issue(sb, cur ^ 1, kvbase, kt + 1, tid);
            CP_COMMIT();
            CP_WAIT1();
        } else {
            CP_WAIT0();
        }
        __syncthreads();

        const uint32_t uKh = sb + (uint32_t)(cur * AT_STAGE + 0 * AT_TILE) * 2;
        const uint32_t uKl = sb + (uint32_t)(cur * AT_STAGE + 1 * AT_TILE) * 2;
        const uint32_t uVh = sb + (uint32_t)(cur * AT_STAGE + 2 * AT_TILE) * 2;
        const uint32_t uVl = sb + (uint32_t)(cur * AT_STAGE + 3 * AT_TILE) * 2;

        // ---- S = Q K^T
        float s[8][4];
        #pragma unroll
        for (int nf = 0; nf < 8; nf++)
            #pragma unroll
            for (int c = 0; c < 4; c++) s[nf][c] = 0.f;

        #pragma unroll
        for (int ks = 0; ks < 4; ks++) {
            uint32_t kbh[4][4], kbl[4][4];
            const int row = ((lane >> 4) & 1) * 8 + (lane & 7);
            const int kk  = ks * 16 + ((lane >> 3) & 1) * 8;
            #pragma unroll
            for (int nb = 0; nb < 4; nb++) {
                const uint32_t off =
                    (uint32_t)(((nb * 16 + row) * AT_STRIDE + kk) * 2);
                ldsm_x4(kbh[nb], uKh + off);
                ldsm_x4(kbl[nb], uKl + off);
            }
            #pragma unroll
            for (int nf = 0; nf < 8; nf++) {
                const int nb = nf >> 1, oo = (nf & 1) * 2;
                mma16816(s[nf], qh[ks], &kbh[nb][oo]);
                mma16816(s[nf], qh[ks], &kbl[nb][oo]);
                mma16816(s[nf], ql[ks], &kbh[nb][oo]);
            }
        }

        // ---- online softmax
        float mn0 = m0, mn1 = m1;
        #pragma unroll
        for (int nf = 0; nf < 8; nf++) {
            mn0 = fmaxf(mn0, fmaxf(s[nf][0], s[nf][1]));
            mn1 = fmaxf(mn1, fmaxf(s[nf][2], s[nf][3]));
        }
        mn0 = fmaxf(mn0, __shfl_xor_sync(0xffffffffu, mn0, 1));
        mn0 = fmaxf(mn0, __shfl_xor_sync(0xffffffffu, mn0, 2));
        mn1 = fmaxf(mn1, __shfl_xor_sync(0xffffffffu, mn1, 1));
        mn1 = fmaxf(mn1, __shfl_xor_sync(0xffffffffu, mn1, 2));
        const float c0 = __expf(m0 - mn0);
        const float c1 = __expf(m1 - mn1);
        m0 = mn0; m1 = mn1;
        l0 *= c0;  l1 *= c1;
        #pragma unroll
        for (int nf = 0; nf < 8; nf++) {
            o[nf][0] *= c0; o[nf][1] *= c0;
            o[nf][2] *= c1; o[nf][3] *= c1;
        }

        // ---- P = exp(S - m), split into A-fragments
        uint32_t pah[4][4], pal[4][4];
        #pragma unroll
        for (int nf = 0; nf < 8; nf++) {
            const float p0 = __expf(s[nf][0] - m0);
            const float p1 = __expf(s[nf][1] - m0);
            const float p2 = __expf(s[nf][2] - m1);
            const float p3 = __expf(s[nf][3] - m1);
            l0 += p0 + p1;
            l1 += p2 + p3;
            __nv_bfloat16 h0 = __float2bfloat16(p0), h1 = __float2bfloat16(p1);
            __nv_bfloat16 h2 = __float2bfloat16(p2), h3 = __float2bfloat16(p3);
            const int ks = nf >> 1, base = (nf & 1) * 2;
            pah[ks][base + 0] = pack_bf16x2(p0, p1);
            pah[ks][base + 1] = pack_bf16x2(p2, p3);
            pal[ks][base + 0] = pack_bf16x2(p0 - __bfloat162float(h0),
                                            p1 - __bfloat162float(h1));
            pal[ks][base + 1] = pack_bf16x2(p2 - __bfloat162float(h2),
                                            p3 - __bfloat162float(h3));
        }

        // ---- O += P V
        #pragma unroll
        for (int ks = 0; ks < 4; ks++) {
            const int krow = ks * 16 + ((lane >> 3) & 1) * 8 + (lane & 7);
            #pragma unroll
            for (int half = 0; half < 2; half++) {
                uint32_t vbh[2][4], vbl[2][4];
                #pragma unroll
                for (int nb = 0; nb < 2; nb++) {
                    const int dh = half * 32 + nb * 16 + ((lane >> 4) & 1) * 8;
                    const uint32_t off = (uint32_t)((krow * AT_STRIDE + dh) * 2);
                    ldsm_x4_t(vbh[nb], uVh + off);
                    ldsm_x4_t(vbl[nb], uVl + off);
                }
                #pragma unroll
                for (int nf = 0; nf < 4; nf++) {
                    const int nb = nf >> 1, oo = (nf & 1) * 2;
                    mma16816(o[half * 4 + nf], pah[ks], &vbh[nb][oo]);
                    mma16816(o[half * 4 + nf], pah[ks], &vbl[nb][oo]);
                    mma16816(o[half * 4 + nf], pal[ks], &vbh[nb][oo]);
                }
            }
        }
        __syncthreads();
    }

    // ---- finalize
    l0 += __shfl_xor_sync(0xffffffffu, l0, 1);
    l0 += __shfl_xor_sync(0xffffffffu, l0, 2);
    l1 += __shfl_xor_sync(0xffffffffu, l1, 1);
    l1 += __shfl_xor_sync(0xffffffffu, l1, 2);
    const float inv0 = 1.0f / l0, inv1 = 1.0f / l1;

    const int b = bh >> 4, h = bh & 15;
    const int row0 = qbase + warp_m + (lane >> 2);
    const int ec = (lane & 3) * 2;
    #pragma unroll
    for (int nf = 0; nf < 8; nf++) {
        const int dh = nf * 8 + ec;
        split2_store(g_oh, g_ol,
                     (size_t)(b * SEQ + row0) * D_MODEL + h * 64 + dh,
                     o[nf][0] * inv0, o[nf][1] * inv0);
        split2_store(g_oh, g_ol,
                     (size_t)(b * SEQ + row0 + 8) * D_MODEL + h * 64 + dh,
                     o[nf][2] * inv1, o[nf][3] * inv1);
    }
}

// ---------------------------------------------------------------------------
extern "C" void kernel_launch(void* const* d_in, const int* in_sizes, int n_in,
                              void* d_out, int out_size)
{
    const float* x  = (const float*)d_in[0];
    const float* Wq = (const float*)d_in[1];
    const float* bq = (const float*)d_in[2];
    const float* Wk = (const float*)d_in[3];
    const float* bk = (const float*)d_in[4];
    const float* Wv = (const float*)d_in[5];
    const float* bv = (const float*)d_in[6];
    const float* Wo = (const float*)d_in[7];
    const float* bo = (const float*)d_in[8];
    float* out = (float*)d_out;

    static int attr_done = 0;
    if (!attr_done) {
        cudaFuncSetAttribute(qkv_gemm_kernel,
                             cudaFuncAttributeMaxDynamicSharedMemorySize, GEMM_SMEM_B);
        cudaFuncSetAttribute(out_gemm_kernel,
                             cudaFuncAttributeMaxDynamicSharedMemorySize, GEMM_SMEM_B);
        cudaFuncSetAttribute(attn_kernel,
                             cudaFuncAttributeMaxDynamicSharedMemorySize, ATTN_SMEM_B);
        attr_done = 1;
    }

    // device-global pointers (host side)
    __nv_bfloat16 *xh, *xl, *wqh, *wql, *wkh, *wkl, *wvh, *wvl, *woh, *wol;
    cudaGetSymbolAddress((void**)&xh,  g_xh);  cudaGetSymbolAddress((void**)&xl,  g_xl);
    cudaGetSymbolAddress((void**)&wqh, g_wqh); cudaGetSymbolAddress((void**)&wql, g_wql);
    cudaGetSymbolAddress((void**)&wkh, g_wkh); cudaGetSymbolAddress((void**)&wkl, g_wkl);
    cudaGetSymbolAddress((void**)&wvh, g_wvh); cudaGetSymbolAddress((void**)&wvl, g_wvl);
    cudaGetSymbolAddress((void**)&woh, g_woh); cudaGetSymbolAddress((void**)&wol, g_wol);

    // split passes
    split_kernel<<<1024, 256>>>(x,  xh,  xl,  M_TOTAL * D_MODEL / 4);
    split_kernel<<<256,  256>>>(Wq, wqh, wql, D_MODEL * D_MODEL / 4);
    split_kernel<<<256,  256>>>(Wk, wkh, wkl, D_MODEL * D_MODEL / 4);
    split_kernel<<<256,  256>>>(Wv, wvh, wvl, D_MODEL * D_MODEL / 4);
    split_kernel<<<256,  256>>>(Wo, woh, wol, D_MODEL * D_MODEL / 4);

    // QKV projections
    dim3 gqkv(D_MODEL / 128, M_TOTAL / 128, 3);
    qkv_gemm_kernel<<<gqkv, 256, GEMM_SMEM_B>>>(bq, bk, bv);

    // Attention
    dim3 gattn(BATCH * NUM_HEADS, SEQ / 64);
    attn_kernel<<<gattn, 128, ATTN_SMEM_B>>>();

    // Output projection
    dim3 gout(D_MODEL / 128, M_TOTAL / 128);
    out_gemm_kernel<<<gout, 256, GEMM_SMEM_B>>>(bo, out);
}